// round 12
// baseline (speedup 1.0000x reference)
#include <cuda_runtime.h>
#include <math.h>

#define NN 50000
#define EE 800000
#define QDIM 128
#define PDIM 64
#define NH 8
#define HDM 16
#define FD 128   // NH*HDM
#define NTILES ((NN + 63) / 64)   // 782

typedef unsigned long long ull;

// ---------------- scratch (device globals; no runtime allocation) ----------
__device__ float g_qh[(size_t)NN * FD];
__device__ float g_kh[(size_t)NN * FD];
__device__ float g_vh[(size_t)NN * FD];
__device__ float g_bias[(size_t)EE * NH];

// CSR sort scratch
__device__ int  g_cnt[NN];
__device__ int  g_excl[NN];
__device__ int  g_bsum[256];
__device__ int  g_rowptr[NN + 1];
__device__ int  g_cursor[NN];
__device__ int2 g_sb[EE];        // (src, edge-id) per sorted slot

// ---------------- packed f32x2 helpers (sm_103a FFMA2 path) ----------------
__device__ __forceinline__ ull splat2(float x) {
    ull r; asm("mov.b64 %0, {%1, %1};" : "=l"(r) : "f"(x)); return r;
}
__device__ __forceinline__ void fma2(ull& d, ull a, ull b) {
    asm("fma.rn.f32x2 %0, %1, %2, %0;" : "+l"(d) : "l"(a), "l"(b));
}
__device__ __forceinline__ void unpack2(ull p, float& lo, float& hi) {
    asm("mov.b64 {%0, %1}, %2;" : "=f"(lo), "=f"(hi) : "l"(p));
}

// ---------------- init: zero histogram --------------------------------------
__global__ void k_init() {
    int i = blockIdx.x * blockDim.x + threadIdx.x;
    if (i < NN) g_cnt[i] = 0;
}

// ---------------- CSR build: histogram, scan, scatter ------------------------
__global__ void k_hist(const int* __restrict__ ei) {
    int e = blockIdx.x * blockDim.x + threadIdx.x;
    if (e < EE) {
        int dst = ((const int2*)ei)[e].x;
        atomicAdd(&g_cnt[dst], 1);
    }
}

__global__ void k_scan1() {        // per-block inclusive scan of counts
    __shared__ int s[256];
    int tid = threadIdx.x;
    int i = blockIdx.x * 256 + tid;
    int v = (i < NN) ? g_cnt[i] : 0;
    s[tid] = v;
    __syncthreads();
#pragma unroll
    for (int off = 1; off < 256; off <<= 1) {
        int t = (tid >= off) ? s[tid - off] : 0;
        __syncthreads();
        s[tid] += t;
        __syncthreads();
    }
    if (i < NN) g_excl[i] = s[tid] - v;
    if (tid == 255) g_bsum[blockIdx.x] = s[255];
}

__global__ void k_scan2(int nblk) { // exclusive scan of block sums (<=256)
    __shared__ int s[256];
    int tid = threadIdx.x;
    int v = (tid < nblk) ? g_bsum[tid] : 0;
    s[tid] = v;
    __syncthreads();
#pragma unroll
    for (int off = 1; off < 256; off <<= 1) {
        int t = (tid >= off) ? s[tid - off] : 0;
        __syncthreads();
        s[tid] += t;
        __syncthreads();
    }
    if (tid < nblk) g_bsum[tid] = s[tid] - v;
}

__global__ void k_scan3() {
    int i = blockIdx.x * 256 + threadIdx.x;
    if (i < NN) {
        int r = g_excl[i] + g_bsum[blockIdx.x];
        g_rowptr[i] = r;
        g_cursor[i] = r;
    }
    if (i == 0) g_rowptr[NN] = EE;
}

__global__ void k_scatter(const int* __restrict__ ei) {
    int e = blockIdx.x * blockDim.x + threadIdx.x;
    if (e < EE) {
        int2 de = ((const int2*)ei)[e];
        int pos = atomicAdd(&g_cursor[de.x], 1);
        g_sb[pos] = make_int2(de.y, e);
    }
}

// ---------------- GEMM tiles ------------------------------------------------
#define SW 132                 // padded smem stride (words)

// 256-thread variant: thread = 4 rows x 8 cols (used by k_proj)
#define K_STEP(kk)                                                        \
    {                                                                     \
        ulonglong2 w01 = *(const ulonglong2*)&Ws[(k4 + kk) * SW + c0];    \
        ulonglong2 w23 = *(const ulonglong2*)&Ws[(k4 + kk) * SW + c0 + 4];\
        _Pragma("unroll")                                                 \
        for (int i = 0; i < 4; i++) {                                     \
            ull s = splat2(((const float*)&a[i])[kk]);                    \
            fma2(acc[i][0], s, w01.x); fma2(acc[i][1], s, w01.y);         \
            fma2(acc[i][2], s, w23.x); fma2(acc[i][3], s, w23.y);         \
        }                                                                 \
    }

// 512-thread variant: thread = 2 rows x 8 cols (used by k_edgeout)
#define K_STEPF(kk)                                                       \
    {                                                                     \
        ulonglong2 w01 = *(const ulonglong2*)&Ws[(k4 + kk) * SW + c0];    \
        ulonglong2 w23 = *(const ulonglong2*)&Ws[(k4 + kk) * SW + c0 + 4];\
        _Pragma("unroll")                                                 \
        for (int i = 0; i < 2; i++) {                                     \
            ull s = splat2(((const float*)&a[i])[kk]);                    \
            fma2(acc[i][0], s, w01.x); fma2(acc[i][1], s, w01.y);         \
            fma2(acc[i][2], s, w23.x); fma2(acc[i][3], s, w23.y);         \
        }                                                                 \
    }

// persistent blocks: W loaded once, loop over row tiles
__global__ __launch_bounds__(256) void k_proj(
    const float* __restrict__ q, const float* __restrict__ k,
    const float* __restrict__ v, const float* __restrict__ Wq,
    const float* __restrict__ Wk, const float* __restrict__ Wv)
{
    extern __shared__ float sm[];
    float* Ws  = sm;            // 128 x SW
    float* ins = sm + 128 * SW; // 64 x SW

    const float* in; const float* W; float* out; float scale;
    if (blockIdx.y == 0)      { in = q; W = Wq; out = g_qh; scale = 0.25f; }
    else if (blockIdx.y == 1) { in = k; W = Wk; out = g_kh; scale = 1.f; }
    else                      { in = v; W = Wv; out = g_vh; scale = 1.f; }

    int tid = threadIdx.x;
    int rg = tid & 15;
    int cg = tid >> 4;
    int c0 = cg * 8;

#pragma unroll
    for (int i = 0; i < 16; i++) {               // W once per block
        int idx = tid + i * 256;
        int r = idx >> 5, c4 = idx & 31;
        float4 w = ((const float4*)W)[idx];
        w.x *= scale; w.y *= scale; w.z *= scale; w.w *= scale;
        *(float4*)&Ws[r * SW + c4 * 4] = w;
    }

    for (int t = blockIdx.x; t < NTILES; t += gridDim.x) {
        int row0 = t * 64;
        __syncthreads();                         // prev readers done / W ready
#pragma unroll
        for (int i = 0; i < 8; i++) {
            int idx = tid + i * 256;
            int r = idx >> 5, c4 = idx & 31;
            float4 val = make_float4(0.f, 0.f, 0.f, 0.f);
            if (row0 + r < NN)
                val = ((const float4*)(in + (size_t)(row0 + r) * QDIM))[c4];
            *(float4*)&ins[r * SW + c4 * 4] = val;
        }
        __syncthreads();

        ull acc[4][4];
#pragma unroll
        for (int i = 0; i < 4; i++)
#pragma unroll
            for (int j = 0; j < 4; j++) acc[i][j] = 0ull;

        for (int k4 = 0; k4 < 128; k4 += 4) {
            float4 a[4];
#pragma unroll
            for (int i = 0; i < 4; i++)
                a[i] = *(const float4*)&ins[(rg + 16 * i) * SW + k4];
            K_STEP(0) K_STEP(1) K_STEP(2) K_STEP(3)
        }

#pragma unroll
        for (int i = 0; i < 4; i++) {
            int r = row0 + rg + 16 * i;
            if (r < NN) {
                float4 o1, o2;
                unpack2(acc[i][0], o1.x, o1.y); unpack2(acc[i][1], o1.z, o1.w);
                unpack2(acc[i][2], o2.x, o2.y); unpack2(acc[i][3], o2.z, o2.w);
                *(float4*)(out + (size_t)r * FD + c0)     = o1;
                *(float4*)(out + (size_t)r * FD + c0 + 4) = o2;
            }
        }
    }
}

// ---------------- edge bias: g_bias[e,h] = edges[e] . Wb[:,h] + bb[h] -------
__global__ __launch_bounds__(256) void k_ebias(
    const float* __restrict__ edges, const float* __restrict__ Wb,
    const float* __restrict__ bb)
{
    __shared__ float WbT[8][76];
    __shared__ float bbs[8];
    __shared__ float ed[32 * 64];

    int tid = threadIdx.x;
    int e0  = blockIdx.x * 32;

#pragma unroll
    for (int i = 0; i < 2; i++) {
        int t = tid + i * 256;
        if (t < 512) WbT[t & 7][t >> 3] = Wb[t];
    }
    if (tid < 8) bbs[tid] = bb[tid];

#pragma unroll
    for (int i = 0; i < 2; i++) {
        int idx = tid + i * 256;
        ((float4*)ed)[idx] = ((const float4*)(edges + (size_t)e0 * PDIM))[idx];
    }
    __syncthreads();

    int el = tid >> 3;
    int h  = tid & 7;
    float acc = bbs[h];
    const float4* ep = (const float4*)(ed + el * 64);
    const float4* wp = (const float4*)(&WbT[h][0]);
#pragma unroll
    for (int k4 = 0; k4 < 16; k4++) {
        float4 e4 = ep[k4], w4 = wp[k4];
        acc += e4.x * w4.x + e4.y * w4.y + e4.z * w4.z + e4.w * w4.w;
    }
    g_bias[(size_t)e0 * NH + tid] = acc;
}

// ---------------- fused edge pass + output GEMM ------------------------------
// Persistent blocks of 512 threads. Per 64-node tile:
//   phase A: warp-per-node softmax-weighted gather (round-8 depth-1 prefetch),
//            normalized result written straight into the smem GEMM buffer
//   phase B: out[tile] = ins @ Wo + bo  (FFMA2, 2 rows x 8 cols per thread)
// g_o is eliminated; out-GEMM compute overlaps other blocks' edge gathers.
__global__ __launch_bounds__(512) void k_edgeout(
    const float* __restrict__ Wo, const float* __restrict__ bo,
    float* __restrict__ out)
{
    extern __shared__ float sm[];
    float* Ws  = sm;            // 128 x SW
    float* ins = sm + 128 * SW; // 64 x SW

    int tid  = threadIdx.x;
    int lane = tid & 31;
    int wid  = tid >> 5;        // 0..15
    int h    = lane >> 2;

    int rg = tid & 31;          // GEMM rows rg, rg+32
    int cg = tid >> 5;          // 16 col groups x 8 cols
    int c0 = cg * 8;

#pragma unroll
    for (int i = 0; i < 8; i++) {   // Wo once per block (4096 float4 / 512 thr)
        int idx = tid + i * 512;
        int r = idx >> 5, c4 = idx & 31;
        float4 w = ((const float4*)Wo)[idx];
        *(float4*)&Ws[r * SW + c4 * 4] = w;
    }
    float4 b1 = *(const float4*)(bo + c0);
    float4 b2 = *(const float4*)(bo + c0 + 4);

    for (int t = blockIdx.x; t < NTILES; t += gridDim.x) {
        int row0 = t * 64;
        __syncthreads();            // ins free (prev GEMM done) / Ws ready

        // ---- phase A: edge softmax gather, warp wid owns rows wid*4..+3 ----
#pragma unroll 1
        for (int j = 0; j < 4; j++) {
            int r = wid * 4 + j;
            int n = row0 + r;
            float4 acc = make_float4(0.f, 0.f, 0.f, 0.f);
            float den = 0.f;

            if (n < NN) {
                int start = g_rowptr[n];
                int end   = g_rowptr[n + 1];
                float4 qv = ((const float4*)g_qh)[(size_t)n * 32 + lane];

                if (start < end) {
                    int2 sb = g_sb[start];
                    float4 kv = ((const float4*)g_kh)[(size_t)sb.x * 32 + lane];
                    float4 vv = ((const float4*)g_vh)[(size_t)sb.x * 32 + lane];
                    float  bs = g_bias[(size_t)sb.y * NH + h];

                    for (int i = start;;) {
                        float4 kc = kv, vc = vv;
                        float  bc = bs;
                        if (i + 1 < end) {          // prefetch next edge
                            int2 s2 = g_sb[i + 1];
                            kv = ((const float4*)g_kh)[(size_t)s2.x * 32 + lane];
                            vv = ((const float4*)g_vh)[(size_t)s2.x * 32 + lane];
                            bs = g_bias[(size_t)s2.y * NH + h];
                        }
                        float p = qv.x * kc.x + qv.y * kc.y
                                + qv.z * kc.z + qv.w * kc.w;
                        p += __shfl_xor_sync(0xffffffffu, p, 1);
                        p += __shfl_xor_sync(0xffffffffu, p, 2);
                        float ex = __expf(p + bc);
                        den += ex;
                        acc.x += ex * vc.x; acc.y += ex * vc.y;
                        acc.z += ex * vc.z; acc.w += ex * vc.w;
                        if (++i >= end) break;
                    }
                }
            }

            float inv = (den > 0.f) ? 1.f / den : 0.f;
            acc.x *= inv; acc.y *= inv; acc.z *= inv; acc.w *= inv;
            *(float4*)&ins[r * SW + lane * 4] = acc;
        }
        __syncthreads();

        // ---- phase B: out = ins @ Wo + bo ----------------------------------
        ull acc[2][4];
#pragma unroll
        for (int i = 0; i < 2; i++)
#pragma unroll
            for (int j = 0; j < 4; j++) acc[i][j] = 0ull;

        for (int k4 = 0; k4 < 128; k4 += 4) {
            float4 a[2];
#pragma unroll
            for (int i = 0; i < 2; i++)
                a[i] = *(const float4*)&ins[(rg + 32 * i) * SW + k4];
            K_STEPF(0) K_STEPF(1) K_STEPF(2) K_STEPF(3)
        }

#pragma unroll
        for (int i = 0; i < 2; i++) {
            int r = row0 + rg + 32 * i;
            if (r < NN) {
                float4 o1, o2;
                unpack2(acc[i][0], o1.x, o1.y); unpack2(acc[i][1], o1.z, o1.w);
                unpack2(acc[i][2], o2.x, o2.y); unpack2(acc[i][3], o2.z, o2.w);
                o1.x += b1.x; o1.y += b1.y; o1.z += b1.z; o1.w += b1.w;
                o2.x += b2.x; o2.y += b2.y; o2.z += b2.z; o2.w += b2.w;
                *(float4*)(out + (size_t)r * FD + c0)     = o1;
                *(float4*)(out + (size_t)r * FD + c0 + 4) = o2;
            }
        }
    }
}

// ---------------- launch: fork-join overlap of independent phases -----------
static cudaStream_t g_s1 = 0, g_s2 = 0;
static cudaEvent_t  g_ev0 = 0, g_ev1 = 0, g_ev2 = 0;

static void ensure_streams() {
    if (!g_s1) {
        cudaStreamCreateWithFlags(&g_s1, cudaStreamNonBlocking);
        cudaStreamCreateWithFlags(&g_s2, cudaStreamNonBlocking);
        cudaEventCreateWithFlags(&g_ev0, cudaEventDisableTiming);
        cudaEventCreateWithFlags(&g_ev1, cudaEventDisableTiming);
        cudaEventCreateWithFlags(&g_ev2, cudaEventDisableTiming);
    }
}

extern "C" void kernel_launch(void* const* d_in, const int* in_sizes, int n_in,
                              void* d_out, int out_size)
{
    const float* q     = (const float*)d_in[0];
    const float* k     = (const float*)d_in[1];
    const float* v     = (const float*)d_in[2];
    const float* edges = (const float*)d_in[3];
    const int*   ei    = (const int*)d_in[4];
    const float* Wq    = (const float*)d_in[5];
    const float* Wk    = (const float*)d_in[6];
    const float* Wv    = (const float*)d_in[7];
    const float* Wo    = (const float*)d_in[8];
    const float* bo    = (const float*)d_in[9];
    const float* Wb    = (const float*)d_in[10];
    const float* bb    = (const float*)d_in[11];
    float* out = (float*)d_out;

    ensure_streams();

    int smem = (128 * SW + 64 * SW) * (int)sizeof(float);  // ~99 KB
    cudaFuncSetAttribute(k_proj,    cudaFuncAttributeMaxDynamicSharedMemorySize, smem);
    cudaFuncSetAttribute(k_edgeout, cudaFuncAttributeMaxDynamicSharedMemorySize, smem);

    const int nscan = (NN + 255) / 256;   // 196 blocks

    // fork: side streams branch off the (possibly capturing) default stream
    cudaEventRecord(g_ev0, 0);
    cudaStreamWaitEvent(g_s1, g_ev0, 0);
    cudaStreamWaitEvent(g_s2, g_ev0, 0);

    // s1: edge-bias GEMV (DRAM streaming, 205 MB)
    k_ebias<<<EE / 32, 256, 0, g_s1>>>(edges, Wb, bb);

    // s2: CSR build (counting sort by dst; latency-bound chain)
    k_init<<<nscan, 256, 0, g_s2>>>();
    k_hist<<<(EE + 255) / 256, 256, 0, g_s2>>>(ei);
    k_scan1<<<nscan, 256, 0, g_s2>>>();
    k_scan2<<<1, 256, 0, g_s2>>>(nscan);
    k_scan3<<<nscan, 256, 0, g_s2>>>();
    k_scatter<<<(EE + 255) / 256, 256, 0, g_s2>>>(ei);

    // default: node projections (compute-bound FFMA2 GEMM, persistent blocks)
    dim3 gproj(99, 3);
    k_proj<<<gproj, 256, smem>>>(q, k, v, Wq, Wk, Wv);

    // join
    cudaEventRecord(g_ev1, g_s1);
    cudaEventRecord(g_ev2, g_s2);
    cudaStreamWaitEvent(0, g_ev1, 0);
    cudaStreamWaitEvent(0, g_ev2, 0);

    // fused edge softmax-gather + output GEMM (persistent, 2 blocks/SM)
    k_edgeout<<<296, 512, smem>>>(Wo, bo, out);
}

// round 13
// speedup vs baseline: 1.1927x; 1.1927x over previous
#include <cuda_runtime.h>
#include <math.h>

#define NN 50000
#define EE 800000
#define QDIM 128
#define PDIM 64
#define NH 8
#define HDM 16
#define FD 128   // NH*HDM
#define NTILES  ((NN + 63) / 64)    // 782  (k_out tiles)
#define NTILE128 ((NN + 127) / 128) // 391  (k_proj tiles)

typedef unsigned long long ull;

// ---------------- scratch (device globals; no runtime allocation) ----------
__device__ float g_qh[(size_t)NN * FD];
__device__ float g_kh[(size_t)NN * FD];
__device__ float g_vh[(size_t)NN * FD];
__device__ float g_bias[(size_t)EE * NH];
__device__ float g_o[(size_t)NN * FD];

// CSR sort scratch
__device__ int  g_cnt[NN];
__device__ int  g_excl[NN];
__device__ int  g_bsum[256];
__device__ int  g_rowptr[NN + 1];
__device__ int  g_cursor[NN];
__device__ int2 g_sb[EE];        // (src, edge-id) per sorted slot

// ---------------- packed f32x2 helpers (sm_103a FFMA2 path) ----------------
__device__ __forceinline__ ull splat2(float x) {
    ull r; asm("mov.b64 %0, {%1, %1};" : "=l"(r) : "f"(x)); return r;
}
__device__ __forceinline__ void fma2(ull& d, ull a, ull b) {
    asm("fma.rn.f32x2 %0, %1, %2, %0;" : "+l"(d) : "l"(a), "l"(b));
}
__device__ __forceinline__ void unpack2(ull p, float& lo, float& hi) {
    asm("mov.b64 {%0, %1}, %2;" : "=f"(lo), "=f"(hi) : "l"(p));
}

// ---------------- init: zero histogram --------------------------------------
__global__ void k_init() {
    int i = blockIdx.x * blockDim.x + threadIdx.x;
    if (i < NN) g_cnt[i] = 0;
}

// ---------------- CSR build: histogram, scan, scatter ------------------------
__global__ void k_hist(const int* __restrict__ ei) {
    int e = blockIdx.x * blockDim.x + threadIdx.x;
    if (e < EE) {
        int dst = ((const int2*)ei)[e].x;
        atomicAdd(&g_cnt[dst], 1);
    }
}

__global__ void k_scan1() {        // per-block inclusive scan of counts
    __shared__ int s[256];
    int tid = threadIdx.x;
    int i = blockIdx.x * 256 + tid;
    int v = (i < NN) ? g_cnt[i] : 0;
    s[tid] = v;
    __syncthreads();
#pragma unroll
    for (int off = 1; off < 256; off <<= 1) {
        int t = (tid >= off) ? s[tid - off] : 0;
        __syncthreads();
        s[tid] += t;
        __syncthreads();
    }
    if (i < NN) g_excl[i] = s[tid] - v;
    if (tid == 255) g_bsum[blockIdx.x] = s[255];
}

__global__ void k_scan2(int nblk) { // exclusive scan of block sums (<=256)
    __shared__ int s[256];
    int tid = threadIdx.x;
    int v = (tid < nblk) ? g_bsum[tid] : 0;
    s[tid] = v;
    __syncthreads();
#pragma unroll
    for (int off = 1; off < 256; off <<= 1) {
        int t = (tid >= off) ? s[tid - off] : 0;
        __syncthreads();
        s[tid] += t;
        __syncthreads();
    }
    if (tid < nblk) g_bsum[tid] = s[tid] - v;
}

__global__ void k_scan3() {
    int i = blockIdx.x * 256 + threadIdx.x;
    if (i < NN) {
        int r = g_excl[i] + g_bsum[blockIdx.x];
        g_rowptr[i] = r;
        g_cursor[i] = r;
    }
    if (i == 0) g_rowptr[NN] = EE;
}

__global__ void k_scatter(const int* __restrict__ ei) {
    int e = blockIdx.x * blockDim.x + threadIdx.x;
    if (e < EE) {
        int2 de = ((const int2*)ei)[e];
        int pos = atomicAdd(&g_cursor[de.x], 1);
        g_sb[pos] = make_int2(de.y, e);
    }
}

// ---------------- GEMM tiles ------------------------------------------------
#define SW 132                 // padded smem stride (words)

// k_out variant: thread = 4 rows x 8 cols
#define K_STEP(kk)                                                        \
    {                                                                     \
        ulonglong2 w01 = *(const ulonglong2*)&Ws[(k4 + kk) * SW + c0];    \
        ulonglong2 w23 = *(const ulonglong2*)&Ws[(k4 + kk) * SW + c0 + 4];\
        _Pragma("unroll")                                                 \
        for (int i = 0; i < 4; i++) {                                     \
            ull s = splat2(((const float*)&a[i])[kk]);                    \
            fma2(acc[i][0], s, w01.x); fma2(acc[i][1], s, w01.y);         \
            fma2(acc[i][2], s, w23.x); fma2(acc[i][3], s, w23.y);         \
        }                                                                 \
    }

// k_proj variant: thread = 8 rows x 8 cols (1.0 smem-B/MAC; FMA-bound)
#define K_STEP8(kk)                                                       \
    {                                                                     \
        ulonglong2 w01 = *(const ulonglong2*)&Ws[(k4 + kk) * SW + c0];    \
        ulonglong2 w23 = *(const ulonglong2*)&Ws[(k4 + kk) * SW + c0 + 4];\
        _Pragma("unroll")                                                 \
        for (int i = 0; i < 8; i++) {                                     \
            ull s = splat2(((const float*)&a[i])[kk]);                    \
            fma2(acc[i][0], s, w01.x); fma2(acc[i][1], s, w01.y);         \
            fma2(acc[i][2], s, w23.x); fma2(acc[i][3], s, w23.y);         \
        }                                                                 \
    }

// persistent blocks, 128-row tiles, 1 block/SM (132 KB smem)
__global__ __launch_bounds__(256, 1) void k_proj(
    const float* __restrict__ q, const float* __restrict__ k,
    const float* __restrict__ v, const float* __restrict__ Wq,
    const float* __restrict__ Wk, const float* __restrict__ Wv)
{
    extern __shared__ float sm[];
    float* Ws  = sm;             // 128 x SW
    float* ins = sm + 128 * SW;  // 128 x SW

    const float* in; const float* W; float* out; float scale;
    if (blockIdx.y == 0)      { in = q; W = Wq; out = g_qh; scale = 0.25f; }
    else if (blockIdx.y == 1) { in = k; W = Wk; out = g_kh; scale = 1.f; }
    else                      { in = v; W = Wv; out = g_vh; scale = 1.f; }

    int tid = threadIdx.x;
    int rg = tid & 15;          // rows rg + 16*i, i<8
    int cg = tid >> 4;          // 16 col groups x 8 cols
    int c0 = cg * 8;

#pragma unroll
    for (int i = 0; i < 16; i++) {               // W once per block
        int idx = tid + i * 256;
        int r = idx >> 5, c4 = idx & 31;
        float4 w = ((const float4*)W)[idx];
        w.x *= scale; w.y *= scale; w.z *= scale; w.w *= scale;
        *(float4*)&Ws[r * SW + c4 * 4] = w;
    }

    for (int t = blockIdx.x; t < NTILE128; t += gridDim.x) {
        int row0 = t * 128;
        __syncthreads();                         // prev readers done / W ready
#pragma unroll
        for (int i = 0; i < 16; i++) {           // A: 128x128 tile
            int idx = tid + i * 256;
            int r = idx >> 5, c4 = idx & 31;
            float4 val = make_float4(0.f, 0.f, 0.f, 0.f);
            if (row0 + r < NN)
                val = ((const float4*)(in + (size_t)(row0 + r) * QDIM))[c4];
            *(float4*)&ins[r * SW + c4 * 4] = val;
        }
        __syncthreads();

        ull acc[8][4];
#pragma unroll
        for (int i = 0; i < 8; i++)
#pragma unroll
            for (int j = 0; j < 4; j++) acc[i][j] = 0ull;

        for (int k4 = 0; k4 < 128; k4 += 4) {
            float4 a[8];
#pragma unroll
            for (int i = 0; i < 8; i++)
                a[i] = *(const float4*)&ins[(rg + 16 * i) * SW + k4];
            K_STEP8(0) K_STEP8(1) K_STEP8(2) K_STEP8(3)
        }

#pragma unroll
        for (int i = 0; i < 8; i++) {
            int r = row0 + rg + 16 * i;
            if (r < NN) {
                float4 o1, o2;
                unpack2(acc[i][0], o1.x, o1.y); unpack2(acc[i][1], o1.z, o1.w);
                unpack2(acc[i][2], o2.x, o2.y); unpack2(acc[i][3], o2.z, o2.w);
                *(float4*)(out + (size_t)r * FD + c0)     = o1;
                *(float4*)(out + (size_t)r * FD + c0 + 4) = o2;
            }
        }
    }
}

// ---------------- edge bias: g_bias[e,h] = edges[e] . Wb[:,h] + bb[h] -------
__global__ __launch_bounds__(256) void k_ebias(
    const float* __restrict__ edges, const float* __restrict__ Wb,
    const float* __restrict__ bb)
{
    __shared__ float WbT[8][76];
    __shared__ float bbs[8];
    __shared__ float ed[32 * 64];

    int tid = threadIdx.x;
    int e0  = blockIdx.x * 32;

#pragma unroll
    for (int i = 0; i < 2; i++) {
        int t = tid + i * 256;
        if (t < 512) WbT[t & 7][t >> 3] = Wb[t];
    }
    if (tid < 8) bbs[tid] = bb[tid];

#pragma unroll
    for (int i = 0; i < 2; i++) {
        int idx = tid + i * 256;
        ((float4*)ed)[idx] = ((const float4*)(edges + (size_t)e0 * PDIM))[idx];
    }
    __syncthreads();

    int el = tid >> 3;
    int h  = tid & 7;
    float acc = bbs[h];
    const float4* ep = (const float4*)(ed + el * 64);
    const float4* wp = (const float4*)(&WbT[h][0]);
#pragma unroll
    for (int k4 = 0; k4 < 16; k4++) {
        float4 e4 = ep[k4], w4 = wp[k4];
        acc += e4.x * w4.x + e4.y * w4.y + e4.z * w4.z + e4.w * w4.w;
    }
    g_bias[(size_t)e0 * NH + tid] = acc;
}

// ---------------- fused sorted edge pass: warp per destination node ---------
// (round-8 proven version: depth-1 prefetch, no inter-warp coupling)
__global__ __launch_bounds__(256) void k_edge() {
    int lane = threadIdx.x & 31;
    int n = blockIdx.x * 8 + (threadIdx.x >> 5);
    if (n >= NN) return;

    int start = g_rowptr[n];
    int end   = g_rowptr[n + 1];
    int h = lane >> 2;

    float4 qv = ((const float4*)g_qh)[(size_t)n * 32 + lane];
    float4 acc = make_float4(0.f, 0.f, 0.f, 0.f);
    float den = 0.f;

    if (start < end) {
        int2 sb = g_sb[start];
        float4 kv = ((const float4*)g_kh)[(size_t)sb.x * 32 + lane];
        float4 vv = ((const float4*)g_vh)[(size_t)sb.x * 32 + lane];
        float  bs = g_bias[(size_t)sb.y * NH + h];

        for (int i = start;;) {
            float4 kc = kv, vc = vv;
            float  bc = bs;
            if (i + 1 < end) {               // prefetch next edge
                int2 s2 = g_sb[i + 1];
                kv = ((const float4*)g_kh)[(size_t)s2.x * 32 + lane];
                vv = ((const float4*)g_vh)[(size_t)s2.x * 32 + lane];
                bs = g_bias[(size_t)s2.y * NH + h];
            }
            float p = qv.x * kc.x + qv.y * kc.y + qv.z * kc.z + qv.w * kc.w;
            p += __shfl_xor_sync(0xffffffffu, p, 1);
            p += __shfl_xor_sync(0xffffffffu, p, 2);
            float ex = __expf(p + bc);
            den += ex;
            acc.x += ex * vc.x; acc.y += ex * vc.y;
            acc.z += ex * vc.z; acc.w += ex * vc.w;
            if (++i >= end) break;
        }
    }

    float inv = (den > 0.f) ? 1.f / den : 0.f;
    acc.x *= inv; acc.y *= inv; acc.z *= inv; acc.w *= inv;
    ((float4*)g_o)[(size_t)n * 32 + lane] = acc;
}

// ---------------- output GEMM: out = g_o @ Wo + bo (persistent blocks) ------
__global__ __launch_bounds__(256) void k_out(
    const float* __restrict__ Wo, const float* __restrict__ bo,
    float* __restrict__ out)
{
    extern __shared__ float sm[];
    float* Ws  = sm;
    float* ins = sm + 128 * SW;

    int tid = threadIdx.x;
    int rg = tid & 15;
    int cg = tid >> 4;
    int c0 = cg * 8;

#pragma unroll
    for (int i = 0; i < 16; i++) {
        int idx = tid + i * 256;
        int r = idx >> 5, c4 = idx & 31;
        float4 w = ((const float4*)Wo)[idx];
        *(float4*)&Ws[r * SW + c4 * 4] = w;
    }
    float4 b1 = *(const float4*)(bo + c0);
    float4 b2 = *(const float4*)(bo + c0 + 4);

    for (int t = blockIdx.x; t < NTILES; t += gridDim.x) {
        int row0 = t * 64;
        __syncthreads();
#pragma unroll
        for (int i = 0; i < 8; i++) {
            int idx = tid + i * 256;
            int r = idx >> 5, c4 = idx & 31;
            int grow = row0 + r;
            float4 val = make_float4(0.f, 0.f, 0.f, 0.f);
            if (grow < NN)
                val = ((const float4*)(g_o + (size_t)grow * FD))[c4];
            *(float4*)&ins[r * SW + c4 * 4] = val;
        }
        __syncthreads();

        ull acc[4][4];
#pragma unroll
        for (int i = 0; i < 4; i++)
#pragma unroll
            for (int j = 0; j < 4; j++) acc[i][j] = 0ull;

        for (int k4 = 0; k4 < 128; k4 += 4) {
            float4 a[4];
#pragma unroll
            for (int i = 0; i < 4; i++)
                a[i] = *(const float4*)&ins[(rg + 16 * i) * SW + k4];
            K_STEP(0) K_STEP(1) K_STEP(2) K_STEP(3)
        }

#pragma unroll
        for (int i = 0; i < 4; i++) {
            int r = row0 + rg + 16 * i;
            if (r < NN) {
                float4 o1, o2;
                unpack2(acc[i][0], o1.x, o1.y); unpack2(acc[i][1], o1.z, o1.w);
                unpack2(acc[i][2], o2.x, o2.y); unpack2(acc[i][3], o2.z, o2.w);
                o1.x += b1.x; o1.y += b1.y; o1.z += b1.z; o1.w += b1.w;
                o2.x += b2.x; o2.y += b2.y; o2.z += b2.z; o2.w += b2.w;
                *(float4*)(out + (size_t)r * FD + c0)     = o1;
                *(float4*)(out + (size_t)r * FD + c0 + 4) = o2;
            }
        }
    }
}

// ---------------- launch: fork-join overlap of independent phases -----------
static cudaStream_t g_s1 = 0, g_s2 = 0;
static cudaEvent_t  g_ev0 = 0, g_ev1 = 0, g_ev2 = 0;

static void ensure_streams() {
    if (!g_s1) {
        cudaStreamCreateWithFlags(&g_s1, cudaStreamNonBlocking);
        cudaStreamCreateWithFlags(&g_s2, cudaStreamNonBlocking);
        cudaEventCreateWithFlags(&g_ev0, cudaEventDisableTiming);
        cudaEventCreateWithFlags(&g_ev1, cudaEventDisableTiming);
        cudaEventCreateWithFlags(&g_ev2, cudaEventDisableTiming);
    }
}

extern "C" void kernel_launch(void* const* d_in, const int* in_sizes, int n_in,
                              void* d_out, int out_size)
{
    const float* q     = (const float*)d_in[0];
    const float* k     = (const float*)d_in[1];
    const float* v     = (const float*)d_in[2];
    const float* edges = (const float*)d_in[3];
    const int*   ei    = (const int*)d_in[4];
    const float* Wq    = (const float*)d_in[5];
    const float* Wk    = (const float*)d_in[6];
    const float* Wv    = (const float*)d_in[7];
    const float* Wo    = (const float*)d_in[8];
    const float* bo    = (const float*)d_in[9];
    const float* Wb    = (const float*)d_in[10];
    const float* bb    = (const float*)d_in[11];
    float* out = (float*)d_out;

    ensure_streams();

    int smem_proj = (128 * SW + 128 * SW) * (int)sizeof(float); // ~132 KB
    int smem_out  = (128 * SW + 64 * SW) * (int)sizeof(float);  // ~99 KB
    cudaFuncSetAttribute(k_proj, cudaFuncAttributeMaxDynamicSharedMemorySize, smem_proj);
    cudaFuncSetAttribute(k_out,  cudaFuncAttributeMaxDynamicSharedMemorySize, smem_out);

    const int nscan = (NN + 255) / 256;   // 196 blocks

    // fork: side streams branch off the (possibly capturing) default stream
    cudaEventRecord(g_ev0, 0);
    cudaStreamWaitEvent(g_s1, g_ev0, 0);
    cudaStreamWaitEvent(g_s2, g_ev0, 0);

    // s1: edge-bias GEMV (DRAM streaming, 205 MB)
    k_ebias<<<EE / 32, 256, 0, g_s1>>>(edges, Wb, bb);

    // s2: CSR build (counting sort by dst; latency-bound chain)
    k_init<<<nscan, 256, 0, g_s2>>>();
    k_hist<<<(EE + 255) / 256, 256, 0, g_s2>>>(ei);
    k_scan1<<<nscan, 256, 0, g_s2>>>();
    k_scan2<<<1, 256, 0, g_s2>>>(nscan);
    k_scan3<<<nscan, 256, 0, g_s2>>>();
    k_scatter<<<(EE + 255) / 256, 256, 0, g_s2>>>(ei);

    // default: node projections (FMA-bound FFMA2 GEMM, 8x8 thread tiles)
    dim3 gproj(49, 3);
    k_proj<<<gproj, 256, smem_proj>>>(q, k, v, Wq, Wk, Wv);

    // join
    cudaEventRecord(g_ev1, g_s1);
    cudaEventRecord(g_ev2, g_s2);
    cudaStreamWaitEvent(0, g_ev1, 0);
    cudaStreamWaitEvent(0, g_ev2, 0);

    k_edge<<<(NN + 7) / 8, 256>>>();
    k_out<<<296, 256, smem_out>>>(Wo, bo, out);
}